// round 10
// baseline (speedup 1.0000x reference)
#include <cuda_runtime.h>

// Problem constants (fixed by reference setup_inputs)
#define B 8
#define N 256
#define D 128
#define D4 (D / 4)        // 32 float4 per feature row
#define NPL (N / 32)      // 8 nodes per lane

__device__ __forceinline__ float4 f4add(float4 a, float4 b) {
    return make_float4(a.x + b.x, a.y + b.y, a.z + b.z, a.w + b.w);
}

// Warp-autonomous kernel: NO __syncthreads, NO shared memory.
// Each warp owns one (batch b, float4-column col) pair — 256 warp-tasks
// total (B * D4). It loads all 256 nodes of that column (8 per lane),
// reduces across the warp with a 5-step shuffle butterfly, and writes both
// output halves. Warps never interact: the critical path is one warp's own
// loads -> butterfly -> stores, with no slowest-warp barrier coupling.
// Grid: 128 blocks x 64 threads (2 warps/block) ~= one wave on 148 SMs.
__global__ void __launch_bounds__(64, 1)
fused_kernel(const float4* __restrict__ x, float4* __restrict__ out)
{
    const int wg   = blockIdx.x * 2 + (threadIdx.x >> 5);  // 0..255
    const int lane = threadIdx.x & 31;
    const int b    = wg >> 5;            // / D4
    const int col  = wg & (D4 - 1);

    const float4* xb = x + (size_t)b * N * D4;

    // Load 8 nodes (lane, lane+32, ..., lane+224) of this column.
    float4 v[NPL];
    #pragma unroll
    for (int k = 0; k < NPL; ++k)
        v[k] = xb[(lane + 32 * k) * D4 + col];

    const float c1 = 255.0f / 256.0f;
    const float c2 = 1.0f / 256.0f;

    // First half of output is independent of the sum — drain it while the
    // reduction below runs.
    #pragma unroll
    for (int k = 0; k < NPL; ++k) {
        const int n = lane + 32 * k;
        float4 o1;
        o1.x = v[k].x * c1; o1.y = v[k].y * c1;
        o1.z = v[k].z * c1; o1.w = v[k].w * c1;
        out[((size_t)(b * N + n)) * (2 * D4) + col] = o1;
    }

    // Per-lane partial sum (tree over the 8 registers, depth 3).
    float4 a0 = f4add(v[0], v[1]), a1 = f4add(v[2], v[3]);
    float4 a2 = f4add(v[4], v[5]), a3 = f4add(v[6], v[7]);
    float4 acc = f4add(f4add(a0, a1), f4add(a2, a3));

    // Full-warp butterfly: after this every lane holds S[b][col].
    #pragma unroll
    for (int m = 1; m < 32; m <<= 1) {
        acc.x += __shfl_xor_sync(0xffffffffu, acc.x, m);
        acc.y += __shfl_xor_sync(0xffffffffu, acc.y, m);
        acc.z += __shfl_xor_sync(0xffffffffu, acc.z, m);
        acc.w += __shfl_xor_sync(0xffffffffu, acc.w, m);
    }

    // Second half: (S - x) / N.
    #pragma unroll
    for (int k = 0; k < NPL; ++k) {
        const int n = lane + 32 * k;
        float4 o2;
        o2.x = (acc.x - v[k].x) * c2; o2.y = (acc.y - v[k].y) * c2;
        o2.z = (acc.z - v[k].z) * c2; o2.w = (acc.w - v[k].w) * c2;
        out[((size_t)(b * N + n)) * (2 * D4) + D4 + col] = o2;
    }
}

extern "C" void kernel_launch(void* const* d_in, const int* in_sizes, int n_in,
                              void* d_out, int out_size)
{
    const float4* x = (const float4*)d_in[0];   // [B, N, D] fp32
    float4* out = (float4*)d_out;               // [B, N, 2D] fp32
    (void)in_sizes; (void)n_in; (void)out_size;

    fused_kernel<<<(B * D4) / 2, 64>>>(x, out);
}